// round 10
// baseline (speedup 1.0000x reference)
#include <cuda_runtime.h>
#include <cuda_bf16.h>
#include <cstdint>

#define BB 256
#define NN 256
#define MM 256
#define DD 1024
#define RBAND 128
#define BIGF 1e30f

// dist row-major [b][i][j]
__device__ float g_dist[(size_t)BB * 256 * 256];

static __device__ __forceinline__ uint32_t smem_u32(const void* p) {
    uint32_t a;
    asm("{ .reg .u64 t; cvta.to.shared.u64 t, %1; cvt.u32.u64 %0, t; }" : "=r"(a) : "l"(p));
    return a;
}
static __device__ __forceinline__ void cp16(uint32_t dst, const void* src) {
    asm volatile("cp.async.cg.shared.global [%0], [%1], 16;\n" ::"r"(dst), "l"(src) : "memory");
}
static __device__ __forceinline__ void ldsm_x4(uint32_t& r0, uint32_t& r1, uint32_t& r2,
                                               uint32_t& r3, uint32_t addr) {
    asm volatile("ldmatrix.sync.aligned.m8n8.x4.shared.b16 {%0,%1,%2,%3}, [%4];"
                 : "=r"(r0), "=r"(r1), "=r"(r2), "=r"(r3) : "r"(addr));
}
static __device__ __forceinline__ uint4 cvt_f8_bf16(float4 a, float4 b) {
    __nv_bfloat162 p0 = __floats2bfloat162_rn(a.x, a.y);
    __nv_bfloat162 p1 = __floats2bfloat162_rn(a.z, a.w);
    __nv_bfloat162 p2 = __floats2bfloat162_rn(b.x, b.y);
    __nv_bfloat162 p3 = __floats2bfloat162_rn(b.z, b.w);
    uint4 w;
    w.x = *reinterpret_cast<unsigned int*>(&p0);
    w.y = *reinterpret_cast<unsigned int*>(&p1);
    w.z = *reinterpret_cast<unsigned int*>(&p2);
    w.w = *reinterpret_cast<unsigned int*>(&p3);
    return w;
}

// ---------------------------------------------------------------------------
// Fused kernel: normalization + batched GEMM, KT=64 (16 iterations).
// Grid (2,2,B), 128x128 tile, 256 thr (8 warps: 2M x 4N), warp tile 64x32,
// double-buffered smem pad-72 (LDSM phases conflict-free), ldmatrix fragments,
// R4 immediate-consume load pattern (ss+convert at load site, uint4 STS).
// ---------------------------------------------------------------------------
#define KT 64
#define LDP 72
#define AS_ELE (128 * LDP)
#define GEMM_SMEM (4 * AS_ELE * 2 + 256 * 4)   // A(2 bufs)+B(2 bufs) bf16 + invA/invB

__global__ __launch_bounds__(256, 2) void gemm_kernel(const float* __restrict__ s1,
                                                      const float* __restrict__ s2) {
    extern __shared__ __align__(16) char sm_raw[];
    __nv_bfloat16* As = (__nv_bfloat16*)sm_raw;        // [2][128*LDP]
    __nv_bfloat16* Bs = As + 2 * AS_ELE;               // [2][128*LDP]
    float* invA_s = (float*)(Bs + 2 * AS_ELE);         // [128]
    float* invB_s = invA_s + 128;                      // [128]

    int b  = blockIdx.z;
    int i0 = blockIdx.x * 128;
    int j0 = blockIdx.y * 128;
    int t    = threadIdx.x;
    int lane = t & 31;
    int w    = t >> 5;
    int wm = w & 1;
    int wn = w >> 1;
    int gid = lane >> 2;
    int tig = lane & 3;

    const float* Ag = s1 + (size_t)b * NN * DD + (size_t)i0 * DD;
    const float* Bg = s2 + (size_t)b * MM * DD + (size_t)j0 * DD;

    int lr  = t >> 3;        // 0..31 (row within 32-row group)
    int lc2 = (t & 7) * 8;   // k-col 0,8,...,56 (8 elements = 2 float4)

    float acc[4][4][4];
#pragma unroll
    for (int mt = 0; mt < 4; mt++)
#pragma unroll
        for (int nt = 0; nt < 4; nt++)
#pragma unroll
            for (int c = 0; c < 4; c++) acc[mt][nt][c] = 0.f;

    float ssA[4] = {0.f, 0.f, 0.f, 0.f};
    float ssB[4] = {0.f, 0.f, 0.f, 0.f};

    // Prologue: k-tile 0 -> buf 0 (immediate consume: ss + convert at load site).
    int buf = 0;
    {
        float4 fa[4][2], fb[4][2];
#pragma unroll
        for (int r4 = 0; r4 < 4; r4++) {
            const float* ap = Ag + (size_t)(lr + r4 * 32) * DD + lc2;
            const float* bp = Bg + (size_t)(lr + r4 * 32) * DD + lc2;
            fa[r4][0] = *(const float4*)ap;
            fa[r4][1] = *(const float4*)(ap + 4);
            fb[r4][0] = *(const float4*)bp;
            fb[r4][1] = *(const float4*)(bp + 4);
        }
#pragma unroll
        for (int r4 = 0; r4 < 4; r4++) {
            ssA[r4] += fa[r4][0].x*fa[r4][0].x + fa[r4][0].y*fa[r4][0].y + fa[r4][0].z*fa[r4][0].z + fa[r4][0].w*fa[r4][0].w
                     + fa[r4][1].x*fa[r4][1].x + fa[r4][1].y*fa[r4][1].y + fa[r4][1].z*fa[r4][1].z + fa[r4][1].w*fa[r4][1].w;
            ssB[r4] += fb[r4][0].x*fb[r4][0].x + fb[r4][0].y*fb[r4][0].y + fb[r4][0].z*fb[r4][0].z + fb[r4][0].w*fb[r4][0].w
                     + fb[r4][1].x*fb[r4][1].x + fb[r4][1].y*fb[r4][1].y + fb[r4][1].z*fb[r4][1].z + fb[r4][1].w*fb[r4][1].w;
            *(uint4*)&As[buf * AS_ELE + (lr + r4 * 32) * LDP + lc2] = cvt_f8_bf16(fa[r4][0], fa[r4][1]);
            *(uint4*)&Bs[buf * AS_ELE + (lr + r4 * 32) * LDP + lc2] = cvt_f8_bf16(fb[r4][0], fb[r4][1]);
        }
    }
    __syncthreads();

    int a_row_in = (lane & 15);
    int a_koff   = (lane >> 4) * 8;
    int b_row_in = ((lane >> 4) << 3) + (lane & 7);
    int b_koff   = ((lane >> 3) & 1) * 8;

    for (int kt = 0; kt < DD / KT; kt++) {
        int nk = kt + 1;
        uint4 ua[4], ub[4];
        if (nk < DD / KT) {
            float4 fa[4][2], fb[4][2];
#pragma unroll
            for (int r4 = 0; r4 < 4; r4++) {
                const float* ap = Ag + (size_t)(lr + r4 * 32) * DD + nk * KT + lc2;
                const float* bp = Bg + (size_t)(lr + r4 * 32) * DD + nk * KT + lc2;
                fa[r4][0] = *(const float4*)ap;
                fa[r4][1] = *(const float4*)(ap + 4);
                fb[r4][0] = *(const float4*)bp;
                fb[r4][1] = *(const float4*)(bp + 4);
            }
#pragma unroll
            for (int r4 = 0; r4 < 4; r4++) {
                ssA[r4] += fa[r4][0].x*fa[r4][0].x + fa[r4][0].y*fa[r4][0].y + fa[r4][0].z*fa[r4][0].z + fa[r4][0].w*fa[r4][0].w
                         + fa[r4][1].x*fa[r4][1].x + fa[r4][1].y*fa[r4][1].y + fa[r4][1].z*fa[r4][1].z + fa[r4][1].w*fa[r4][1].w;
                ssB[r4] += fb[r4][0].x*fb[r4][0].x + fb[r4][0].y*fb[r4][0].y + fb[r4][0].z*fb[r4][0].z + fb[r4][0].w*fb[r4][0].w
                         + fb[r4][1].x*fb[r4][1].x + fb[r4][1].y*fb[r4][1].y + fb[r4][1].z*fb[r4][1].z + fb[r4][1].w*fb[r4][1].w;
                ua[r4] = cvt_f8_bf16(fa[r4][0], fa[r4][1]);
                ub[r4] = cvt_f8_bf16(fb[r4][0], fb[r4][1]);
            }
        }
#pragma unroll
        for (int kk = 0; kk < KT; kk += 16) {
            uint32_t af[4][4];
            uint32_t bf2[2][4];
#pragma unroll
            for (int mt = 0; mt < 4; mt++) {
                int arow = wm * 64 + mt * 16 + a_row_in;
                uint32_t addr = smem_u32(&As[buf * AS_ELE + arow * LDP + kk + a_koff]);
                ldsm_x4(af[mt][0], af[mt][1], af[mt][2], af[mt][3], addr);
            }
#pragma unroll
            for (int ntp = 0; ntp < 2; ntp++) {
                int brow = wn * 32 + ntp * 16 + b_row_in;
                uint32_t addr = smem_u32(&Bs[buf * AS_ELE + brow * LDP + kk + b_koff]);
                ldsm_x4(bf2[ntp][0], bf2[ntp][1], bf2[ntp][2], bf2[ntp][3], addr);
            }
#pragma unroll
            for (int mt = 0; mt < 4; mt++)
#pragma unroll
                for (int nt = 0; nt < 4; nt++) {
                    uint32_t b0 = bf2[nt >> 1][(nt & 1) * 2];
                    uint32_t b1 = bf2[nt >> 1][(nt & 1) * 2 + 1];
                    asm volatile(
                        "mma.sync.aligned.m16n8k16.row.col.f32.bf16.bf16.f32 "
                        "{%0,%1,%2,%3}, {%4,%5,%6,%7}, {%8,%9}, {%0,%1,%2,%3};\n"
                        : "+f"(acc[mt][nt][0]), "+f"(acc[mt][nt][1]),
                          "+f"(acc[mt][nt][2]), "+f"(acc[mt][nt][3])
                        : "r"(af[mt][0]), "r"(af[mt][1]), "r"(af[mt][2]), "r"(af[mt][3]),
                          "r"(b0), "r"(b1));
                }
        }
        if (nk < DD / KT) {
            int nbuf = buf ^ 1;
#pragma unroll
            for (int r4 = 0; r4 < 4; r4++) {
                *(uint4*)&As[nbuf * AS_ELE + (lr + r4 * 32) * LDP + lc2] = ua[r4];
                *(uint4*)&Bs[nbuf * AS_ELE + (lr + r4 * 32) * LDP + lc2] = ub[r4];
            }
        }
        __syncthreads();
        buf ^= 1;
    }

    // Per-row inverse norms (8 consecutive lanes share each row)
#pragma unroll
    for (int r4 = 0; r4 < 4; r4++) {
#pragma unroll
        for (int o = 1; o < 8; o <<= 1) {
            ssA[r4] += __shfl_xor_sync(0xffffffffu, ssA[r4], o);
            ssB[r4] += __shfl_xor_sync(0xffffffffu, ssB[r4], o);
        }
        if ((lane & 7) == 0) {
            int row = lr + r4 * 32;
            invA_s[row] = 1.0f / fmaxf(sqrtf(ssA[r4]), 1e-12f);
            invB_s[row] = 1.0f / fmaxf(sqrtf(ssB[r4]), 1e-12f);
        }
    }
    __syncthreads();

    float* dT = g_dist + (size_t)b * 65536;
#pragma unroll
    for (int mt = 0; mt < 4; mt++) {
#pragma unroll
        for (int nt = 0; nt < 4; nt++) {
            int li = wm * 64 + mt * 16 + gid;
            int lj = wn * 32 + nt * 8 + tig * 2;
            float ia0 = invA_s[li];
            float ia1 = invA_s[li + 8];
            float ib0 = invB_s[lj];
            float ib1 = invB_s[lj + 1];
            float2 v0, v1;
            v0.x = 1.0f - fminf(fmaxf(acc[mt][nt][0] * ia0 * ib0, -1.f), 1.f);
            v0.y = 1.0f - fminf(fmaxf(acc[mt][nt][1] * ia0 * ib1, -1.f), 1.f);
            v1.x = 1.0f - fminf(fmaxf(acc[mt][nt][2] * ia1 * ib0, -1.f), 1.f);
            v1.y = 1.0f - fminf(fmaxf(acc[mt][nt][3] * ia1 * ib1, -1.f), 1.f);
            int i = i0 + li;
            int j = j0 + lj;
            *(float2*)&dT[(size_t)i * 256 + j]       = v0;
            *(float2*)&dT[(size_t)(i + 8) * 256 + j] = v1;
        }
    }
}

// ---------------------------------------------------------------------------
// Kernel 2: banded DTW, row-streaming min-plus scan (R4 exact — 67.3 us).
// ---------------------------------------------------------------------------
#define SDEPTH 8

__global__ __launch_bounds__(128) void dtw_kernel(float* __restrict__ out) {
    __shared__ float ring[4][SDEPTH][256];
    int w     = threadIdx.x >> 5;
    int lane  = threadIdx.x & 31;
    int batch = blockIdx.x * 4 + w;
    const float* E = g_dist + (size_t)batch * 65536;
    int cbase = lane * 8;

    for (int s = 0; s < SDEPTH; s++) {
        uint32_t sa = smem_u32(&ring[w][s][cbase]);
        const float* src = E + (size_t)s * 256 + cbase;
        cp16(sa, src);
        cp16(sa + 16, src + 4);
        asm volatile("cp.async.commit_group;\n" ::: "memory");
    }

    float prev[8];

    for (int r = 0; r < 256; r++) {
        asm volatile("cp.async.wait_group 7;\n" ::: "memory");
        float e[8];
        const float* slot = &ring[w][r & (SDEPTH - 1)][cbase];
#pragma unroll
        for (int u = 0; u < 8; u++) e[u] = slot[u];

        int nr = r + SDEPTH;
        if (nr < 256) {
            uint32_t sa = smem_u32(&ring[w][nr & (SDEPTH - 1)][cbase]);
            const float* src = E + (size_t)nr * 256 + cbase;
            cp16(sa, src);
            cp16(sa + 16, src + 4);
        }
        asm volatile("cp.async.commit_group;\n" ::: "memory");

        if (r == 0) {
            float ps[8];
            float run = 0.f;
#pragma unroll
            for (int u = 0; u < 8; u++) { run += e[u]; ps[u] = run; }
            float acc = run;
#pragma unroll
            for (int d = 1; d < 32; d <<= 1) {
                float p = __shfl_up_sync(0xffffffffu, acc, d);
                if (lane >= d) acc += p;
            }
            float excl = acc - run;
#pragma unroll
            for (int u = 0; u < 8; u++) {
                float tv = excl + ps[u];
                prev[u] = (cbase + u <= RBAND) ? tv : BIGF;
            }
        } else {
            float pl = __shfl_up_sync(0xffffffffu, prev[7], 1);
            if (lane == 0) pl = BIGF;
            float bb[8], ss[8];
#pragma unroll
            for (int u = 0; u < 8; u++) {
                int c = cbase + u;
                float pjm1 = u ? prev[u - 1] : pl;
                bool ib = (c >= 1) && (c >= r - RBAND) && (c <= r + RBAND);
                bb[u] = ib ? fminf(prev[u], pjm1) + e[u] : BIGF;
                ss[u] = ib ? e[u] : BIGF;
            }
            if (lane == 0) {
                bb[0] = (r <= RBAND) ? prev[0] + e[0] : BIGF;
                ss[0] = BIGF;
            }
            float tl[8], P[8];
            tl[0] = bb[0];
            P[0]  = ss[0];
#pragma unroll
            for (int u = 1; u < 8; u++) {
                tl[u] = fminf(bb[u], tl[u - 1] + ss[u]);
                P[u]  = P[u - 1] + ss[u];
            }
            float S = P[7], T = tl[7];
#pragma unroll
            for (int d = 1; d < 32; d <<= 1) {
                float Sp = __shfl_up_sync(0xffffffffu, S, d);
                float Tp = __shfl_up_sync(0xffffffffu, T, d);
                if (lane >= d) {
                    T = fminf(T, Tp + S);
                    S = S + Sp;
                }
            }
            float cin = __shfl_up_sync(0xffffffffu, T, 1);
            if (lane == 0) cin = BIGF;
#pragma unroll
            for (int u = 0; u < 8; u++) prev[u] = fminf(tl[u], cin + P[u]);
        }
    }

    if (lane == 31) out[batch] = prev[7];
}

// ---------------------------------------------------------------------------
extern "C" void kernel_launch(void* const* d_in, const int* in_sizes, int n_in,
                              void* d_out, int out_size) {
    const float* s1 = (const float*)d_in[0];
    const float* s2 = (const float*)d_in[1];
    float* out = (float*)d_out;

    cudaFuncSetAttribute(gemm_kernel, cudaFuncAttributeMaxDynamicSharedMemorySize, GEMM_SMEM);
    dim3 g(2, 2, BB);
    gemm_kernel<<<g, 256, GEMM_SMEM>>>(s1, s2);

    dtw_kernel<<<64, 128>>>(out);
}

// round 11
// speedup vs baseline: 1.3064x; 1.3064x over previous
#include <cuda_runtime.h>
#include <cuda_bf16.h>
#include <cstdint>

#define BB 256
#define NN 256
#define MM 256
#define DD 1024
#define RBAND 128
#define BIGF 1e30f

// dist row-major [b][i][j]
__device__ float g_dist[(size_t)BB * 256 * 256];

static __device__ __forceinline__ uint32_t smem_u32(const void* p) {
    uint32_t a;
    asm("{ .reg .u64 t; cvta.to.shared.u64 t, %1; cvt.u32.u64 %0, t; }" : "=r"(a) : "l"(p));
    return a;
}
static __device__ __forceinline__ void cp16(uint32_t dst, const void* src) {
    asm volatile("cp.async.cg.shared.global [%0], [%1], 16;\n" ::"r"(dst), "l"(src) : "memory");
}
static __device__ __forceinline__ void ldsm_x4(uint32_t& r0, uint32_t& r1, uint32_t& r2,
                                               uint32_t& r3, uint32_t addr) {
    asm volatile("ldmatrix.sync.aligned.m8n8.x4.shared.b16 {%0,%1,%2,%3}, [%4];"
                 : "=r"(r0), "=r"(r1), "=r"(r2), "=r"(r3) : "r"(addr));
}
static __device__ __forceinline__ uint2 cvt_f4_bf16(float4 a) {
    __nv_bfloat162 p0 = __floats2bfloat162_rn(a.x, a.y);
    __nv_bfloat162 p1 = __floats2bfloat162_rn(a.z, a.w);
    uint2 w;
    w.x = *reinterpret_cast<unsigned int*>(&p0);
    w.y = *reinterpret_cast<unsigned int*>(&p1);
    return w;
}

// ---------------------------------------------------------------------------
// Fused kernel: normalization + batched GEMM (R4 mma core) with cp.async fp32
// STAGING: raw fp32 tiles stream into a 2-stage smem ring (no registers, no
// scoreboard stall); each thread later LDS's exactly the slices it copied,
// accumulates sum-of-squares, converts to bf16 and stores to the (double-
// buffered) mma smem. One __syncthreads per k-iteration.
// ---------------------------------------------------------------------------
#define KT 32
#define LDP 40
#define STG (128 * 32)     // fp32 stage elems per matrix per stage (16KB)
#define BF  (128 * LDP)    // bf16 buf elems per matrix per buf
// dynamic smem: stageA[2]|stageB[2] (f32) + As[2]|Bs[2] (bf16) + invA|invB
#define SM_STAGEA 0
#define SM_STAGEB (2 * STG * 4)
#define SM_AS     (4 * STG * 4)
#define SM_BS     (SM_AS + 2 * BF * 2)
#define SM_INVA   (SM_BS + 2 * BF * 2)
#define SM_INVB   (SM_INVA + 128 * 4)
#define GEMM_SMEM (SM_INVB + 128 * 4)

__global__ __launch_bounds__(256, 2) void gemm_kernel(const float* __restrict__ s1,
                                                      const float* __restrict__ s2) {
    extern __shared__ __align__(16) char sm[];
    float* stageA = (float*)(sm + SM_STAGEA);           // [2][STG]
    float* stageB = (float*)(sm + SM_STAGEB);           // [2][STG]
    __nv_bfloat16* As = (__nv_bfloat16*)(sm + SM_AS);   // [2][BF]
    __nv_bfloat16* Bs = (__nv_bfloat16*)(sm + SM_BS);   // [2][BF]
    float* invA_s = (float*)(sm + SM_INVA);
    float* invB_s = (float*)(sm + SM_INVB);

    int b  = blockIdx.z;
    int i0 = blockIdx.x * 128;
    int j0 = blockIdx.y * 128;
    int t    = threadIdx.x;
    int lane = t & 31;
    int w    = t >> 5;
    int wm = w & 1;
    int wn = w >> 1;
    int gid = lane >> 2;
    int tig = lane & 3;

    const float* Ag = s1 + (size_t)b * NN * DD + (size_t)i0 * DD;
    const float* Bg = s2 + (size_t)b * MM * DD + (size_t)j0 * DD;

    int lr = t >> 3;        // 0..31 (row within 32-row group)
    int lc = (t & 7) * 4;   // k-col 0,4,...,28

    float acc[4][4][4];
#pragma unroll
    for (int mt = 0; mt < 4; mt++)
#pragma unroll
        for (int nt = 0; nt < 4; nt++)
#pragma unroll
            for (int c = 0; c < 4; c++) acc[mt][nt][c] = 0.f;

    float ssA[4] = {0.f, 0.f, 0.f, 0.f};
    float ssB[4] = {0.f, 0.f, 0.f, 0.f};

    // prologue: cp.async tiles 0,1 into stages 0,1 (one commit group per tile)
#pragma unroll
    for (int s = 0; s < 2; s++) {
#pragma unroll
        for (int r4 = 0; r4 < 4; r4++) {
            int row = lr + r4 * 32;
            cp16(smem_u32(&stageA[s * STG + row * 32 + lc]),
                 Ag + (size_t)row * DD + s * KT + lc);
            cp16(smem_u32(&stageB[s * STG + row * 32 + lc]),
                 Bg + (size_t)row * DD + s * KT + lc);
        }
        asm volatile("cp.async.commit_group;\n" ::: "memory");
    }

    int a_row_in = (lane & 15);
    int a_koff   = (lane >> 4) * 8;
    int b_row_in = ((lane >> 4) << 3) + (lane & 7);
    int b_koff   = ((lane >> 3) & 1) * 8;

    for (int kt = 0; kt < DD / KT; kt++) {
        int st = kt & 1;
        // tile kt resident in stage st after this wait (per-thread: we copied
        // exactly the bytes we read below)
        if (kt >= 30) {
            asm volatile("cp.async.wait_group 0;\n" ::: "memory");
        } else {
            asm volatile("cp.async.wait_group 1;\n" ::: "memory");
        }

        // convert stage st -> bf16 buf st, accumulate sum-of-squares
#pragma unroll
        for (int r4 = 0; r4 < 4; r4++) {
            int row = lr + r4 * 32;
            float4 a4 = *(const float4*)&stageA[st * STG + row * 32 + lc];
            float4 b4 = *(const float4*)&stageB[st * STG + row * 32 + lc];
            ssA[r4] += a4.x * a4.x + a4.y * a4.y + a4.z * a4.z + a4.w * a4.w;
            ssB[r4] += b4.x * b4.x + b4.y * b4.y + b4.z * b4.z + b4.w * b4.w;
            *(uint2*)&As[st * BF + row * LDP + lc] = cvt_f4_bf16(a4);
            *(uint2*)&Bs[st * BF + row * LDP + lc] = cvt_f4_bf16(b4);
        }

        // refill stage st with tile kt+2
        if (kt + 2 < DD / KT) {
#pragma unroll
            for (int r4 = 0; r4 < 4; r4++) {
                int row = lr + r4 * 32;
                cp16(smem_u32(&stageA[st * STG + row * 32 + lc]),
                     Ag + (size_t)row * DD + (kt + 2) * KT + lc);
                cp16(smem_u32(&stageB[st * STG + row * 32 + lc]),
                     Bg + (size_t)row * DD + (kt + 2) * KT + lc);
            }
            asm volatile("cp.async.commit_group;\n" ::: "memory");
        }

        __syncthreads();

        // MMA over bf16 buf st (R4 core)
#pragma unroll
        for (int kk = 0; kk < KT; kk += 16) {
            uint32_t af[4][4];
            uint32_t bf2[2][4];
#pragma unroll
            for (int mt = 0; mt < 4; mt++) {
                int arow = wm * 64 + mt * 16 + a_row_in;
                uint32_t addr = smem_u32(&As[st * BF + arow * LDP + kk + a_koff]);
                ldsm_x4(af[mt][0], af[mt][1], af[mt][2], af[mt][3], addr);
            }
#pragma unroll
            for (int ntp = 0; ntp < 2; ntp++) {
                int brow = wn * 32 + ntp * 16 + b_row_in;
                uint32_t addr = smem_u32(&Bs[st * BF + brow * LDP + kk + b_koff]);
                ldsm_x4(bf2[ntp][0], bf2[ntp][1], bf2[ntp][2], bf2[ntp][3], addr);
            }
#pragma unroll
            for (int mt = 0; mt < 4; mt++)
#pragma unroll
                for (int nt = 0; nt < 4; nt++) {
                    uint32_t b0 = bf2[nt >> 1][(nt & 1) * 2];
                    uint32_t b1 = bf2[nt >> 1][(nt & 1) * 2 + 1];
                    asm volatile(
                        "mma.sync.aligned.m16n8k16.row.col.f32.bf16.bf16.f32 "
                        "{%0,%1,%2,%3}, {%4,%5,%6,%7}, {%8,%9}, {%0,%1,%2,%3};\n"
                        : "+f"(acc[mt][nt][0]), "+f"(acc[mt][nt][1]),
                          "+f"(acc[mt][nt][2]), "+f"(acc[mt][nt][3])
                        : "r"(af[mt][0]), "r"(af[mt][1]), "r"(af[mt][2]), "r"(af[mt][3]),
                          "r"(b0), "r"(b1));
                }
        }
    }

    // Per-row inverse norms (8 consecutive lanes share each row)
#pragma unroll
    for (int r4 = 0; r4 < 4; r4++) {
#pragma unroll
        for (int o = 1; o < 8; o <<= 1) {
            ssA[r4] += __shfl_xor_sync(0xffffffffu, ssA[r4], o);
            ssB[r4] += __shfl_xor_sync(0xffffffffu, ssB[r4], o);
        }
        if ((lane & 7) == 0) {
            int row = lr + r4 * 32;
            invA_s[row] = 1.0f / fmaxf(sqrtf(ssA[r4]), 1e-12f);
            invB_s[row] = 1.0f / fmaxf(sqrtf(ssB[r4]), 1e-12f);
        }
    }
    __syncthreads();

    float* dT = g_dist + (size_t)b * 65536;
#pragma unroll
    for (int mt = 0; mt < 4; mt++) {
#pragma unroll
        for (int nt = 0; nt < 4; nt++) {
            int li = wm * 64 + mt * 16 + gid;
            int lj = wn * 32 + nt * 8 + tig * 2;
            float ia0 = invA_s[li];
            float ia1 = invA_s[li + 8];
            float ib0 = invB_s[lj];
            float ib1 = invB_s[lj + 1];
            float2 v0, v1;
            v0.x = 1.0f - fminf(fmaxf(acc[mt][nt][0] * ia0 * ib0, -1.f), 1.f);
            v0.y = 1.0f - fminf(fmaxf(acc[mt][nt][1] * ia0 * ib1, -1.f), 1.f);
            v1.x = 1.0f - fminf(fmaxf(acc[mt][nt][2] * ia1 * ib0, -1.f), 1.f);
            v1.y = 1.0f - fminf(fmaxf(acc[mt][nt][3] * ia1 * ib1, -1.f), 1.f);
            int i = i0 + li;
            int j = j0 + lj;
            *(float2*)&dT[(size_t)i * 256 + j]       = v0;
            *(float2*)&dT[(size_t)(i + 8) * 256 + j] = v1;
        }
    }
}

// ---------------------------------------------------------------------------
// Kernel 2: banded DTW, row-streaming min-plus scan (R4 exact — 67.3 us).
// ---------------------------------------------------------------------------
#define SDEPTH 8

__global__ __launch_bounds__(128) void dtw_kernel(float* __restrict__ out) {
    __shared__ float ring[4][SDEPTH][256];
    int w     = threadIdx.x >> 5;
    int lane  = threadIdx.x & 31;
    int batch = blockIdx.x * 4 + w;
    const float* E = g_dist + (size_t)batch * 65536;
    int cbase = lane * 8;

    for (int s = 0; s < SDEPTH; s++) {
        uint32_t sa = smem_u32(&ring[w][s][cbase]);
        const float* src = E + (size_t)s * 256 + cbase;
        cp16(sa, src);
        cp16(sa + 16, src + 4);
        asm volatile("cp.async.commit_group;\n" ::: "memory");
    }

    float prev[8];

    for (int r = 0; r < 256; r++) {
        asm volatile("cp.async.wait_group 7;\n" ::: "memory");
        float e[8];
        const float* slot = &ring[w][r & (SDEPTH - 1)][cbase];
#pragma unroll
        for (int u = 0; u < 8; u++) e[u] = slot[u];

        int nr = r + SDEPTH;
        if (nr < 256) {
            uint32_t sa = smem_u32(&ring[w][nr & (SDEPTH - 1)][cbase]);
            const float* src = E + (size_t)nr * 256 + cbase;
            cp16(sa, src);
            cp16(sa + 16, src + 4);
        }
        asm volatile("cp.async.commit_group;\n" ::: "memory");

        if (r == 0) {
            float ps[8];
            float run = 0.f;
#pragma unroll
            for (int u = 0; u < 8; u++) { run += e[u]; ps[u] = run; }
            float acc = run;
#pragma unroll
            for (int d = 1; d < 32; d <<= 1) {
                float p = __shfl_up_sync(0xffffffffu, acc, d);
                if (lane >= d) acc += p;
            }
            float excl = acc - run;
#pragma unroll
            for (int u = 0; u < 8; u++) {
                float tv = excl + ps[u];
                prev[u] = (cbase + u <= RBAND) ? tv : BIGF;
            }
        } else {
            float pl = __shfl_up_sync(0xffffffffu, prev[7], 1);
            if (lane == 0) pl = BIGF;
            float bb[8], ss[8];
#pragma unroll
            for (int u = 0; u < 8; u++) {
                int c = cbase + u;
                float pjm1 = u ? prev[u - 1] : pl;
                bool ib = (c >= 1) && (c >= r - RBAND) && (c <= r + RBAND);
                bb[u] = ib ? fminf(prev[u], pjm1) + e[u] : BIGF;
                ss[u] = ib ? e[u] : BIGF;
            }
            if (lane == 0) {
                bb[0] = (r <= RBAND) ? prev[0] + e[0] : BIGF;
                ss[0] = BIGF;
            }
            float tl[8], P[8];
            tl[0] = bb[0];
            P[0]  = ss[0];
#pragma unroll
            for (int u = 1; u < 8; u++) {
                tl[u] = fminf(bb[u], tl[u - 1] + ss[u]);
                P[u]  = P[u - 1] + ss[u];
            }
            float S = P[7], T = tl[7];
#pragma unroll
            for (int d = 1; d < 32; d <<= 1) {
                float Sp = __shfl_up_sync(0xffffffffu, S, d);
                float Tp = __shfl_up_sync(0xffffffffu, T, d);
                if (lane >= d) {
                    T = fminf(T, Tp + S);
                    S = S + Sp;
                }
            }
            float cin = __shfl_up_sync(0xffffffffu, T, 1);
            if (lane == 0) cin = BIGF;
#pragma unroll
            for (int u = 0; u < 8; u++) prev[u] = fminf(tl[u], cin + P[u]);
        }
    }

    if (lane == 31) out[batch] = prev[7];
}

// ---------------------------------------------------------------------------
extern "C" void kernel_launch(void* const* d_in, const int* in_sizes, int n_in,
                              void* d_out, int out_size) {
    const float* s1 = (const float*)d_in[0];
    const float* s2 = (const float*)d_in[1];
    float* out = (float*)d_out;

    cudaFuncSetAttribute(gemm_kernel, cudaFuncAttributeMaxDynamicSharedMemorySize, GEMM_SMEM);
    dim3 g(2, 2, BB);
    gemm_kernel<<<g, 256, GEMM_SMEM>>>(s1, s2);

    dtw_kernel<<<64, 128>>>(out);
}

// round 12
// speedup vs baseline: 1.3306x; 1.0185x over previous
#include <cuda_runtime.h>
#include <cuda_bf16.h>
#include <cstdint>

#define BB 256
#define NN 256
#define MM 256
#define DD 1024
#define RBAND 128
#define BIGF 1e30f

// dist row-major [b][i][j]
__device__ float g_dist[(size_t)BB * 256 * 256];

static __device__ __forceinline__ uint32_t smem_u32(const void* p) {
    uint32_t a;
    asm("{ .reg .u64 t; cvta.to.shared.u64 t, %1; cvt.u32.u64 %0, t; }" : "=r"(a) : "l"(p));
    return a;
}
static __device__ __forceinline__ void cp16(uint32_t dst, const void* src) {
    asm volatile("cp.async.cg.shared.global [%0], [%1], 16;\n" ::"r"(dst), "l"(src) : "memory");
}
static __device__ __forceinline__ void ldsm_x4(uint32_t& r0, uint32_t& r1, uint32_t& r2,
                                               uint32_t& r3, uint32_t addr) {
    asm volatile("ldmatrix.sync.aligned.m8n8.x4.shared.b16 {%0,%1,%2,%3}, [%4];"
                 : "=r"(r0), "=r"(r1), "=r"(r2), "=r"(r3) : "r"(addr));
}
static __device__ __forceinline__ uint2 cvt_f4_bf16(float4 a) {
    __nv_bfloat162 p0 = __floats2bfloat162_rn(a.x, a.y);
    __nv_bfloat162 p1 = __floats2bfloat162_rn(a.z, a.w);
    uint2 w;
    w.x = *reinterpret_cast<unsigned int*>(&p0);
    w.y = *reinterpret_cast<unsigned int*>(&p1);
    return w;
}

// ---------------------------------------------------------------------------
// Fused kernel (R11 exact — known good): normalization + batched GEMM with
// cp.async fp32 staging ring.
// ---------------------------------------------------------------------------
#define KT 32
#define LDP 40
#define STG (128 * 32)
#define BF  (128 * LDP)
#define SM_STAGEA 0
#define SM_STAGEB (2 * STG * 4)
#define SM_AS     (4 * STG * 4)
#define SM_BS     (SM_AS + 2 * BF * 2)
#define SM_INVA   (SM_BS + 2 * BF * 2)
#define SM_INVB   (SM_INVA + 128 * 4)
#define GEMM_SMEM (SM_INVB + 128 * 4)

__global__ __launch_bounds__(256, 2) void gemm_kernel(const float* __restrict__ s1,
                                                      const float* __restrict__ s2) {
    extern __shared__ __align__(16) char sm[];
    float* stageA = (float*)(sm + SM_STAGEA);
    float* stageB = (float*)(sm + SM_STAGEB);
    __nv_bfloat16* As = (__nv_bfloat16*)(sm + SM_AS);
    __nv_bfloat16* Bs = (__nv_bfloat16*)(sm + SM_BS);
    float* invA_s = (float*)(sm + SM_INVA);
    float* invB_s = (float*)(sm + SM_INVB);

    int b  = blockIdx.z;
    int i0 = blockIdx.x * 128;
    int j0 = blockIdx.y * 128;
    int t    = threadIdx.x;
    int lane = t & 31;
    int w    = t >> 5;
    int wm = w & 1;
    int wn = w >> 1;
    int gid = lane >> 2;
    int tig = lane & 3;

    const float* Ag = s1 + (size_t)b * NN * DD + (size_t)i0 * DD;
    const float* Bg = s2 + (size_t)b * MM * DD + (size_t)j0 * DD;

    int lr = t >> 3;
    int lc = (t & 7) * 4;

    float acc[4][4][4];
#pragma unroll
    for (int mt = 0; mt < 4; mt++)
#pragma unroll
        for (int nt = 0; nt < 4; nt++)
#pragma unroll
            for (int c = 0; c < 4; c++) acc[mt][nt][c] = 0.f;

    float ssA[4] = {0.f, 0.f, 0.f, 0.f};
    float ssB[4] = {0.f, 0.f, 0.f, 0.f};

#pragma unroll
    for (int s = 0; s < 2; s++) {
#pragma unroll
        for (int r4 = 0; r4 < 4; r4++) {
            int row = lr + r4 * 32;
            cp16(smem_u32(&stageA[s * STG + row * 32 + lc]),
                 Ag + (size_t)row * DD + s * KT + lc);
            cp16(smem_u32(&stageB[s * STG + row * 32 + lc]),
                 Bg + (size_t)row * DD + s * KT + lc);
        }
        asm volatile("cp.async.commit_group;\n" ::: "memory");
    }

    int a_row_in = (lane & 15);
    int a_koff   = (lane >> 4) * 8;
    int b_row_in = ((lane >> 4) << 3) + (lane & 7);
    int b_koff   = ((lane >> 3) & 1) * 8;

    for (int kt = 0; kt < DD / KT; kt++) {
        int st = kt & 1;
        if (kt >= 30) {
            asm volatile("cp.async.wait_group 0;\n" ::: "memory");
        } else {
            asm volatile("cp.async.wait_group 1;\n" ::: "memory");
        }

#pragma unroll
        for (int r4 = 0; r4 < 4; r4++) {
            int row = lr + r4 * 32;
            float4 a4 = *(const float4*)&stageA[st * STG + row * 32 + lc];
            float4 b4 = *(const float4*)&stageB[st * STG + row * 32 + lc];
            ssA[r4] += a4.x * a4.x + a4.y * a4.y + a4.z * a4.z + a4.w * a4.w;
            ssB[r4] += b4.x * b4.x + b4.y * b4.y + b4.z * b4.z + b4.w * b4.w;
            *(uint2*)&As[st * BF + row * LDP + lc] = cvt_f4_bf16(a4);
            *(uint2*)&Bs[st * BF + row * LDP + lc] = cvt_f4_bf16(b4);
        }

        if (kt + 2 < DD / KT) {
#pragma unroll
            for (int r4 = 0; r4 < 4; r4++) {
                int row = lr + r4 * 32;
                cp16(smem_u32(&stageA[st * STG + row * 32 + lc]),
                     Ag + (size_t)row * DD + (kt + 2) * KT + lc);
                cp16(smem_u32(&stageB[st * STG + row * 32 + lc]),
                     Bg + (size_t)row * DD + (kt + 2) * KT + lc);
            }
            asm volatile("cp.async.commit_group;\n" ::: "memory");
        }

        __syncthreads();

#pragma unroll
        for (int kk = 0; kk < KT; kk += 16) {
            uint32_t af[4][4];
            uint32_t bf2[2][4];
#pragma unroll
            for (int mt = 0; mt < 4; mt++) {
                int arow = wm * 64 + mt * 16 + a_row_in;
                uint32_t addr = smem_u32(&As[st * BF + arow * LDP + kk + a_koff]);
                ldsm_x4(af[mt][0], af[mt][1], af[mt][2], af[mt][3], addr);
            }
#pragma unroll
            for (int ntp = 0; ntp < 2; ntp++) {
                int brow = wn * 32 + ntp * 16 + b_row_in;
                uint32_t addr = smem_u32(&Bs[st * BF + brow * LDP + kk + b_koff]);
                ldsm_x4(bf2[ntp][0], bf2[ntp][1], bf2[ntp][2], bf2[ntp][3], addr);
            }
#pragma unroll
            for (int mt = 0; mt < 4; mt++)
#pragma unroll
                for (int nt = 0; nt < 4; nt++) {
                    uint32_t b0 = bf2[nt >> 1][(nt & 1) * 2];
                    uint32_t b1 = bf2[nt >> 1][(nt & 1) * 2 + 1];
                    asm volatile(
                        "mma.sync.aligned.m16n8k16.row.col.f32.bf16.bf16.f32 "
                        "{%0,%1,%2,%3}, {%4,%5,%6,%7}, {%8,%9}, {%0,%1,%2,%3};\n"
                        : "+f"(acc[mt][nt][0]), "+f"(acc[mt][nt][1]),
                          "+f"(acc[mt][nt][2]), "+f"(acc[mt][nt][3])
                        : "r"(af[mt][0]), "r"(af[mt][1]), "r"(af[mt][2]), "r"(af[mt][3]),
                          "r"(b0), "r"(b1));
                }
        }
    }

#pragma unroll
    for (int r4 = 0; r4 < 4; r4++) {
#pragma unroll
        for (int o = 1; o < 8; o <<= 1) {
            ssA[r4] += __shfl_xor_sync(0xffffffffu, ssA[r4], o);
            ssB[r4] += __shfl_xor_sync(0xffffffffu, ssB[r4], o);
        }
        if ((lane & 7) == 0) {
            int row = lr + r4 * 32;
            invA_s[row] = 1.0f / fmaxf(sqrtf(ssA[r4]), 1e-12f);
            invB_s[row] = 1.0f / fmaxf(sqrtf(ssB[r4]), 1e-12f);
        }
    }
    __syncthreads();

    float* dT = g_dist + (size_t)b * 65536;
#pragma unroll
    for (int mt = 0; mt < 4; mt++) {
#pragma unroll
        for (int nt = 0; nt < 4; nt++) {
            int li = wm * 64 + mt * 16 + gid;
            int lj = wn * 32 + nt * 8 + tig * 2;
            float ia0 = invA_s[li];
            float ia1 = invA_s[li + 8];
            float ib0 = invB_s[lj];
            float ib1 = invB_s[lj + 1];
            float2 v0, v1;
            v0.x = 1.0f - fminf(fmaxf(acc[mt][nt][0] * ia0 * ib0, -1.f), 1.f);
            v0.y = 1.0f - fminf(fmaxf(acc[mt][nt][1] * ia0 * ib1, -1.f), 1.f);
            v1.x = 1.0f - fminf(fmaxf(acc[mt][nt][2] * ia1 * ib0, -1.f), 1.f);
            v1.y = 1.0f - fminf(fmaxf(acc[mt][nt][3] * ia1 * ib1, -1.f), 1.f);
            int i = i0 + li;
            int j = j0 + lj;
            *(float2*)&dT[(size_t)i * 256 + j]       = v0;
            *(float2*)&dT[(size_t)(i + 8) * 256 + j] = v1;
        }
    }
}

// ---------------------------------------------------------------------------
// Kernel 2: banded DTW — systolic staircase (R7/R8-verified cell math, no warp
// scan) with an 8-DEEP FULLY-UNROLLED REGISTER RING: LDG.128 issued 8 steps
// ahead of use (cover ~8x115 cyc > DRAM latency; 16 outstanding/lane << cap;
// compile-time slot indices -> pure registers, no smem, no wait_group).
// Lane L processes row r = t - L at step t; cross-lane deps via one shfl pair.
// ---------------------------------------------------------------------------
__global__ __launch_bounds__(128) void dtw_kernel(float* __restrict__ out) {
    int w     = threadIdx.x >> 5;
    int lane  = threadIdx.x & 31;
    int batch = blockIdx.x * 4 + w;
    const float* E = g_dist + (size_t)batch * 65536;
    int jb = lane * 8;

    float d1[8];
#pragma unroll
    for (int u = 0; u < 8; u++) d1[u] = BIGF;
    float last7 = BIGF, prev7 = BIGF;
    float result = 0.f;

    float4 pf[8][2];
    // prologue: slot p <- row (p - lane), valid iff lane <= p
#pragma unroll
    for (int p = 0; p < 8; p++) {
        int r = p - lane;
        if (r >= 0) {
            const float* src = E + (size_t)r * 256 + jb;
            pf[p][0] = *(const float4*)src;
            pf[p][1] = *(const float4*)(src + 4);
        }
    }

#pragma unroll 1
    for (int tb = 0; tb < 288; tb += 8) {
#pragma unroll
        for (int p = 0; p < 8; p++) {
            int t = tb + p;
            int r = t - lane;
            bool act = (r >= 0) && (r < 256);

            float e[8];
            e[0] = pf[p][0].x; e[1] = pf[p][0].y; e[2] = pf[p][0].z; e[3] = pf[p][0].w;
            e[4] = pf[p][1].x; e[5] = pf[p][1].y; e[6] = pf[p][1].z; e[7] = pf[p][1].w;

            // refill slot p with row r+8 (consumed at step t+8) — off-chain
            {
                int rl = r + 8;
                if ((unsigned)rl < 256u) {
                    const float* src = E + (size_t)rl * 256 + jb;
                    pf[p][0] = *(const float4*)src;
                    pf[p][1] = *(const float4*)(src + 4);
                }
            }

            // neighbor values from lane L-1 (committed at steps t-1 / t-2)
            float lf0 = __shfl_up_sync(0xffffffffu, last7, 1);  // (r,   jb-1)
            float ul0 = __shfl_up_sync(0xffffffffu, prev7, 1);  // (r-1, jb-1)

            float m[8];
            m[0] = fminf(d1[0], ul0);
#pragma unroll
            for (int u = 1; u < 8; u++) m[u] = fminf(d1[u], d1[u - 1]);

            float nv[8];
            if (lane == 0) {
                nv[0] = (r == 0) ? e[0] : ((r <= RBAND) ? d1[0] + e[0] : BIGF);
            } else {
                bool ib = (jb >= r - RBAND) && (jb <= r + RBAND);
                nv[0] = ib ? fminf(m[0], lf0) + e[0] : BIGF;
            }
#pragma unroll
            for (int u = 1; u < 8; u++) {
                int j = jb + u;
                bool ib = (j >= r - RBAND) && (j <= r + RBAND);
                nv[u] = ib ? fminf(m[u], nv[u - 1]) + e[u] : BIGF;
            }

            if (act) {
#pragma unroll
                for (int u = 0; u < 8; u++) d1[u] = nv[u];
                prev7 = last7;
                last7 = nv[7];
                if (r == 255) result = nv[7];
            }
        }
    }

    if (lane == 31) out[batch] = result;
}

// ---------------------------------------------------------------------------
extern "C" void kernel_launch(void* const* d_in, const int* in_sizes, int n_in,
                              void* d_out, int out_size) {
    const float* s1 = (const float*)d_in[0];
    const float* s2 = (const float*)d_in[1];
    float* out = (float*)d_out;

    cudaFuncSetAttribute(gemm_kernel, cudaFuncAttributeMaxDynamicSharedMemorySize, GEMM_SMEM);
    dim3 g(2, 2, BB);
    gemm_kernel<<<g, 256, GEMM_SMEM>>>(s1, s2);

    dtw_kernel<<<64, 128>>>(out);
}